// round 10
// baseline (speedup 1.0000x reference)
#include <cuda_runtime.h>

// SU2Attention: batch=1, seq=2048, heads=8, spinor_dim=2 (complex).
// Per head: Q=K are 4-dim real unit vectors u_j = s_j/||s_j||, logits u_i.u_j
// scaled by 1/sqrt(2) (bounded -> no max subtraction), softmax over keys,
// values are raw 4-vectors s_j.
//
// Output layout (verified R5-R9): PLANAR — real plane (2048*8*2 floats) then
// imag plane. d_in[0]=real, d_in[1]=imag.
//
// R10: BLOCK=512 -> 128 regs/thread so the unrolled mainloop actually
// pipelines (R9 post-mortem: 64-reg cap at BLOCK=1024 serialized the chains).
// Both key tiles stored pre-duplicated (x,x,y,y)(z,z,w,w) so query-pair
// packed dots AND pair-packed accumulation need zero duplication MOVs:
// per key / 4 queries: 4 LDS.128 + 18 fma-pipe (8 dot FFMA2, 8 acc FFMA2,
// 2 den FADD2) + 4 MUFU.EX2.

#define SEQ    2048
#define HEADS  8
#define QTILE  128
#define BLOCK  512
#define NWARP  (BLOCK / 32)         // 16 splits
#define JCHUNK (SEQ / NWARP)        // 128 keys per warp

typedef unsigned long long u64_t;

__device__ __forceinline__ float2 fmul2(float2 a, float2 b) {
    float2 d;
    asm("mul.rn.f32x2 %0, %1, %2;"
        : "=l"(reinterpret_cast<u64_t&>(d))
        : "l"(reinterpret_cast<const u64_t&>(a)),
          "l"(reinterpret_cast<const u64_t&>(b)));
    return d;
}

__device__ __forceinline__ float2 ffma2(float2 a, float2 b, float2 c) {
    float2 d;
    asm("fma.rn.f32x2 %0, %1, %2, %3;"
        : "=l"(reinterpret_cast<u64_t&>(d))
        : "l"(reinterpret_cast<const u64_t&>(a)),
          "l"(reinterpret_cast<const u64_t&>(b)),
          "l"(reinterpret_cast<const u64_t&>(c)));
    return d;
}

__device__ __forceinline__ float2 fadd2(float2 a, float2 b) {
    float2 d;
    asm("add.rn.f32x2 %0, %1, %2;"
        : "=l"(reinterpret_cast<u64_t&>(d))
        : "l"(reinterpret_cast<const u64_t&>(a)),
          "l"(reinterpret_cast<const u64_t&>(b)));
    return d;
}

__device__ __forceinline__ float ex2_approx(float x) {
    float r;
    asm("ex2.approx.ftz.f32 %0, %1;" : "=f"(r) : "f"(x));
    return r;
}

__global__ __launch_bounds__(BLOCK, 1)
void su2_attn_kernel(const float* __restrict__ p0,   // spinors_real
                     const float* __restrict__ p1,   // spinors_imag
                     float* __restrict__ out) {
    // Dynamic shared (168 KB):
    //   sud:  2*SEQ float4, dup unit vecs (x,x,y,y),(z,z,w,w)   (64 KB)
    //   svd:  2*SEQ float4, dup raw  vecs (x,x,y,y),(z,z,w,w)   (64 KB)
    //   pacc: NWARP x QTILE float4 partials                     (32 KB)
    //   pden: NWARP x QTILE float  partials                     ( 8 KB)
    extern __shared__ float4 smem[];
    float4* sud  = smem;                                  // [2*SEQ]
    float4* svd  = smem + 2 * SEQ;                        // [2*SEQ]
    float4* pacc = smem + 4 * SEQ;                        // [NWARP][QTILE]
    float*  pden = reinterpret_cast<float*>(pacc + NWARP * QTILE);

    const int h    = blockIdx.y;
    const int q0   = blockIdx.x * QTILE;
    const int lane = threadIdx.x & 31;
    const int warp = threadIdx.x >> 5;

    // Cooperative load + normalize of all SEQ vectors for this head.
    for (int j = threadIdx.x; j < SEQ; j += BLOCK) {
        const int base = (j * HEADS + h) * 2;
        float2 a = *reinterpret_cast<const float2*>(p0 + base);  // real (d0,d1)
        float2 b = *reinterpret_cast<const float2*>(p1 + base);  // imag (d0,d1)
        float x = a.x, y = a.y, z = b.x, w = b.y;
        float n2 = x*x + y*y + z*z + w*w;
        float rn = rsqrtf(n2);
        svd[2*j]   = make_float4(x, x, y, y);
        svd[2*j+1] = make_float4(z, z, w, w);
        float ux = x * rn, uy = y * rn, uz = z * rn, uw = w * rn;
        sud[2*j]   = make_float4(ux, ux, uy, uy);
        sud[2*j+1] = make_float4(uz, uz, uw, uw);
    }
    __syncthreads();

    // Each thread owns 4 queries as 2 pairs: pair p = (q0+lane+64p,
    // q0+lane+64p+32). Fold SCALE*log2(e) into the query components.
    const float C = 0.70710678118654752f * 1.44269504088896341f;
    float2 qpx[2], qpy[2], qpz[2], qpw[2];
    #pragma unroll
    for (int p = 0; p < 2; ++p) {
        const int qa = q0 + lane + 64 * p;
        const int qb = qa + 32;
        // raw components from duplicated store: (x at .x, y at .z) etc.
        float4 a0 = svd[2*qa], a1 = svd[2*qa+1];
        float4 b0 = svd[2*qb], b1 = svd[2*qb+1];
        float rna = rsqrtf(a0.x*a0.x + a0.z*a0.z + a1.x*a1.x + a1.z*a1.z) * C;
        float rnb = rsqrtf(b0.x*b0.x + b0.z*b0.z + b1.x*b1.x + b1.z*b1.z) * C;
        qpx[p] = make_float2(a0.x * rna, b0.x * rnb);
        qpy[p] = make_float2(a0.z * rna, b0.z * rnb);
        qpz[p] = make_float2(a1.x * rna, b1.x * rnb);
        qpw[p] = make_float2(a1.z * rna, b1.z * rnb);
    }

    // Pair-packed accumulators: acc{c}[p] = (sum_c for qA, sum_c for qB).
    float2 accx[2], accy[2], accz[2], accw[2], den[2];
    #pragma unroll
    for (int p = 0; p < 2; ++p) {
        accx[p] = accy[p] = accz[p] = accw[p] = den[p] = make_float2(0.f, 0.f);
    }

    const int jlo = warp * JCHUNK;
    #pragma unroll 4
    for (int j = jlo; j < jlo + JCHUNK; ++j) {
        float4 uxy = sud[2*j];                 // (ux,ux,uy,uy)
        float4 uzw = sud[2*j+1];               // (uz,uz,uw,uw)
        float4 vxy = svd[2*j];                 // (vx,vx,vy,vy)
        float4 vzw = svd[2*j+1];               // (vz,vz,vw,vw)
        float2 uxx = make_float2(uxy.x, uxy.y);
        float2 uyy = make_float2(uxy.z, uxy.w);
        float2 uzz = make_float2(uzw.x, uzw.y);
        float2 uww = make_float2(uzw.z, uzw.w);
        float2 vxx = make_float2(vxy.x, vxy.y);
        float2 vyy = make_float2(vxy.z, vxy.w);
        float2 vzz = make_float2(vzw.x, vzw.y);
        float2 vww = make_float2(vzw.z, vzw.w);

        // packed dots: t[p] = (dot qA, dot qB)
        float2 t0 = fmul2(qpx[0], uxx);
        float2 t1 = fmul2(qpx[1], uxx);
        t0 = ffma2(qpy[0], uyy, t0);
        t1 = ffma2(qpy[1], uyy, t1);
        t0 = ffma2(qpz[0], uzz, t0);
        t1 = ffma2(qpz[1], uzz, t1);
        t0 = ffma2(qpw[0], uww, t0);
        t1 = ffma2(qpw[1], uww, t1);

        // exp pairs land directly in register pairs — no duplication MOVs
        float2 e0, e1;
        e0.x = ex2_approx(t0.x);
        e0.y = ex2_approx(t0.y);
        e1.x = ex2_approx(t1.x);
        e1.y = ex2_approx(t1.y);

        accx[0] = ffma2(e0, vxx, accx[0]);
        accy[0] = ffma2(e0, vyy, accy[0]);
        accz[0] = ffma2(e0, vzz, accz[0]);
        accw[0] = ffma2(e0, vww, accw[0]);
        accx[1] = ffma2(e1, vxx, accx[1]);
        accy[1] = ffma2(e1, vyy, accy[1]);
        accz[1] = ffma2(e1, vzz, accz[1]);
        accw[1] = ffma2(e1, vww, accw[1]);
        den[0] = fadd2(den[0], e0);
        den[1] = fadd2(den[1], e1);
    }

    // Write per-warp partials: pair p, half b -> query lane + 64p + 32b.
    #pragma unroll
    for (int p = 0; p < 2; ++p) {
        const int qa = lane + 64 * p;
        pacc[warp * QTILE + qa] =
            make_float4(accx[p].x, accy[p].x, accz[p].x, accw[p].x);
        pden[warp * QTILE + qa] = den[p].x;
        pacc[warp * QTILE + qa + 32] =
            make_float4(accx[p].y, accy[p].y, accz[p].y, accw[p].y);
        pden[warp * QTILE + qa + 32] = den[p].y;
    }
    __syncthreads();

    // Stage A: 4 groups of 4 splits -> 4 partials per query.
    {
        const int q = threadIdx.x & (QTILE - 1);
        const int g = threadIdx.x >> 7;              // 0..3
        const int s0 = g * 4;
        float4 a = pacc[s0 * QTILE + q];
        float  d = pden[s0 * QTILE + q];
        #pragma unroll
        for (int s = 1; s < 4; ++s) {
            float4 b = pacc[(s0 + s) * QTILE + q];
            a.x += b.x; a.y += b.y; a.z += b.z; a.w += b.w;
            d += pden[(s0 + s) * QTILE + q];
        }
        __syncthreads();
        pacc[s0 * QTILE + q] = a;
        pden[s0 * QTILE + q] = d;
    }
    __syncthreads();

    // Stage B: 128 threads finish the 4-way sum, normalize, store planar.
    if (threadIdx.x < QTILE) {
        const int q = threadIdx.x;
        float4 a = pacc[q];
        float  d = pden[q];
        #pragma unroll
        for (int g = 1; g < 4; ++g) {
            float4 b = pacc[g * 4 * QTILE + q];
            a.x += b.x; a.y += b.y; a.z += b.z; a.w += b.w;
            d += pden[g * 4 * QTILE + q];
        }
        const float inv = __frcp_rn(d);
        const int ohd = (q0 + q) * HEADS + h;
        // planar complex: real plane then imag plane, each (1,2048,8,2)
        *reinterpret_cast<float2*>(out + ohd * 2) =
            make_float2(a.x * inv, a.y * inv);
        *reinterpret_cast<float2*>(out + SEQ * HEADS * 2 + ohd * 2) =
            make_float2(a.z * inv, a.w * inv);
    }
}

extern "C" void kernel_launch(void* const* d_in, const int* in_sizes, int n_in,
                              void* d_out, int out_size) {
    const float* p0 = (const float*)d_in[0];
    const float* p1 = (const float*)d_in[1];
    float* out = (float*)d_out;

    const int shmem = 4 * SEQ * sizeof(float4)              // sud + svd
                    + NWARP * QTILE * sizeof(float4)        // pacc
                    + NWARP * QTILE * sizeof(float);        // pden
    cudaFuncSetAttribute(su2_attn_kernel,
                         cudaFuncAttributeMaxDynamicSharedMemorySize, shmem);

    dim3 grid(SEQ / QTILE, HEADS);
    dim3 block(BLOCK);
    su2_attn_kernel<<<grid, block, shmem>>>(p0, p1, out);
}